// round 9
// baseline (speedup 1.0000x reference)
#include <cuda_runtime.h>

#define B_    16384
#define T_    64
#define NB    12         // batch elems per CTA
#define NTHR  384        // 24 groups (12 elems x 2 dirs) x 16 lanes
#define EPAD  2050       // floats per elem tile: 64*32 + 2 pad (bank skew)

typedef unsigned long long u64;

#define L2E 1.4426950408889634f

struct Smem {
    u64   wi[2][48][17];          // [dir][gate_row][k-pair], padded stride 17
    u64   wh[2][48][9];           // [dir][gate_row][k-pair], padded stride 9
    float actA[NB][EPAD];
    float actB[NB][EPAD];
    float bR[2][16], bZ[2][16], bNX[2][16], bNH[2][16];
    float wcw[4][32];
    float wcb[4];
};

__device__ __forceinline__ u64 pack2(float lo, float hi) {
    u64 r; asm("mov.b64 %0, {%1, %2};" : "=l"(r) : "f"(lo), "f"(hi)); return r;
}
__device__ __forceinline__ void unpack2(u64 d, float& lo, float& hi) {
    asm("mov.b64 {%0, %1}, %2;" : "=f"(lo), "=f"(hi) : "l"(d));
}
__device__ __forceinline__ u64 ffma2(u64 a, u64 b, u64 c) {
    u64 d; asm("fma.rn.f32x2 %0, %1, %2, %3;" : "=l"(d) : "l"(a), "l"(b), "l"(c)); return d;
}
__device__ __forceinline__ u64 add2(u64 a, u64 b) {
    u64 d; asm("add.rn.f32x2 %0, %1, %2;" : "=l"(d) : "l"(a), "l"(b)); return d;
}
__device__ __forceinline__ float hadd(u64 v) {
    float lo, hi; unpack2(v, lo, hi); return lo + hi;
}
__device__ __forceinline__ float ex2(float x) {
    float r; asm("ex2.approx.ftz.f32 %0, %1;" : "=f"(r) : "f"(x)); return r;
}
__device__ __forceinline__ float rcp(float x) {
    float r; asm("rcp.approx.ftz.f32 %0, %1;" : "=f"(r) : "f"(x)); return r;
}
// s pre-scaled by log2e: sigmoid(x) = 1/(1+2^-s)
__device__ __forceinline__ float sigm2(float s) {
    return rcp(1.f + ex2(-s));
}
// s pre-scaled by 2*log2e: tanh(x) = sign * (1-2^-|s|)/(1+2^-|s|)
__device__ __forceinline__ float tanh2(float s) {
    float a = fabsf(s);
    float e = ex2(-a);
    float t = (1.f - e) * rcp(1.f + e);
    return copysignf(t, s);
}

// Stage one layer's weights into smem as f32x2 pairs, pre-scaled by log2e
// (r,z rows) / 2*log2e (n rows) so gate nonlinearities use raw ex2.
__device__ __forceinline__ void stage_layer(Smem* s,
        const float* __restrict__ Wi, const float* __restrict__ Wh,
        const float* __restrict__ bi, const float* __restrict__ bh,
        int F, int KP, int tid)
{
    for (int i = tid; i < 2 * 48 * KP; i += NTHR) {
        int d = i / (48 * KP); int r = i - d * 48 * KP;
        int row = r / KP, kp = r - row * KP;
        float sc = (row < 32) ? L2E : 2.f * L2E;
        const float* w = Wi + ((size_t)d * 48 + row) * F;
        float lo = w[2 * kp] * sc;
        float hi = (2 * kp + 1 < F) ? w[2 * kp + 1] * sc : 0.f;
        s->wi[d][row][kp] = pack2(lo, hi);
    }
    for (int i = tid; i < 2 * 48 * 8; i += NTHR) {
        int d = i / (48 * 8); int r = i - d * 48 * 8;
        int row = r >> 3, kp = r & 7;
        float sc = (row < 32) ? L2E : 2.f * L2E;
        const float* w = Wh + ((size_t)d * 48 + row) * 16;
        s->wh[d][row][kp] = pack2(w[2 * kp] * sc, w[2 * kp + 1] * sc);
    }
    for (int i = tid; i < 2 * 16; i += NTHR) {
        int d = i >> 4, uu = i & 15;
        s->bR[d][uu]  = (bi[d * 48 + uu]      + bh[d * 48 + uu])      * L2E;
        s->bZ[d][uu]  = (bi[d * 48 + 16 + uu] + bh[d * 48 + 16 + uu]) * L2E;
        s->bNX[d][uu] = bi[d * 48 + 32 + uu] * 2.f * L2E;
        s->bNH[d][uu] = bh[d * 48 + 32 + uu] * 2.f * L2E;
    }
}

// One bidirectional GRU layer. Lane u of 16-lane group (elem,dir) owns hidden
// unit u. Recurrence via register shfl (width 16). r/z weights in registers;
// n-gate weights streamed from smem (conflict-free broadcast LDS) to stay
// under the 170-reg ceiling at 384 threads. Input gemm for step t+1 is
// computed inside step t (software pipeline) to fill the gate-chain stalls.
template <int KP>
__device__ __forceinline__ void run_layer(Smem* s,
        const float (*rd)[EPAD], float (*wr)[EPAD],
        int elem, int dir, int u)
{
    u64 wir[KP], wiz[KP];
#pragma unroll
    for (int k = 0; k < KP; k++) {
        wir[k] = s->wi[dir][u][k];
        wiz[k] = s->wi[dir][16 + u][k];
    }
    u64 whr[8], whz[8];
#pragma unroll
    for (int k = 0; k < 8; k++) {
        whr[k] = s->wh[dir][u][k];
        whz[k] = s->wh[dir][16 + u][k];
    }
    const u64* __restrict__ winp = &s->wi[dir][32 + u][0];  // streamed
    const u64* __restrict__ whnp = &s->wh[dir][32 + u][0];  // streamed
    const float br  = s->bR[dir][u],  bz  = s->bZ[dir][u];
    const float bnx = s->bNX[dir][u], bnh = s->bNH[dir][u];
    const int wcol = dir * 16 + u;
    const int stp  = dir ? -1 : 1;

    u64 xar, xaz, xan;
    // x-gemm for step t (biases folded into accumulator init)
    auto xgemm = [&](int t) {
        const u64* xp = (const u64*)&rd[elem][t * 32];
        u64 r = pack2(br, 0.f), z = pack2(bz, 0.f), n = pack2(bnx, 0.f);
#pragma unroll
        for (int k = 0; k < KP; k++) {
            u64 xv = xp[k];
            r = ffma2(wir[k], xv, r);
            z = ffma2(wiz[k], xv, z);
            n = ffma2(winp[k], xv, n);
        }
        xar = r; xaz = z; xan = n;
    };

    int t = dir ? (T_ - 1) : 0;
    xgemm(t);

    // ---- peeled first step (h == 0, no recurrence) ----
    float h;
    {
        float r = sigm2(hadd(xar));
        float z = sigm2(hadd(xaz));
        float n = tanh2(fmaf(r, bnh, hadd(xan)));
        h = fmaf(-z, n, n);                      // (1-z)*n
        wr[elem][t * 32 + wcol] = h;
        t += stp;
        xgemm(t);                                // pipeline: x-acc for step 1
    }

#pragma unroll 1
    for (int ti = 1; ti < T_; ++ti) {
        // recurrent gemm: gather group's h via shfl (width 16), pack to f32x2
        u64 arh = 0, azh = 0, anh = 0;
#pragma unroll
        for (int k = 0; k < 8; k++) {
            float h0 = __shfl_sync(0xffffffffu, h, 2 * k,     16);
            float h1 = __shfl_sync(0xffffffffu, h, 2 * k + 1, 16);
            u64 hv = pack2(h0, h1);
            arh = ffma2(whr[k], hv, arh);
            azh = ffma2(whz[k], hv, azh);
            anh = ffma2(whnp[k], hv, anh);
        }
        float arf  = hadd(add2(xar, arh));
        float azf  = hadd(add2(xaz, azh));
        float anxf = hadd(xan);
        float anhf = hadd(anh) + bnh;

        // pipeline: x-acc for next step (independent -> fills gate stalls)
        int tn = (ti == T_ - 1) ? t : t + stp;
        xgemm(tn);

        float r = sigm2(arf);
        float z = sigm2(azf);
        float n = tanh2(fmaf(r, anhf, anxf));
        h = fmaf(z, h - n, n);                   // (1-z)*n + z*h
        wr[elem][t * 32 + wcol] = h;
        t = tn;
    }
}

extern "C" __global__ void __launch_bounds__(NTHR)
fused_gru(const float* __restrict__ x,
          const float* __restrict__ Wi1, const float* __restrict__ Wh1,
          const float* __restrict__ bi1, const float* __restrict__ bh1,
          const float* __restrict__ Wi5, const float* __restrict__ Wh5,
          const float* __restrict__ bi5, const float* __restrict__ bh5,
          const float* __restrict__ Wc,  const float* __restrict__ bc,
          float* __restrict__ out)
{
    extern __shared__ __align__(16) unsigned char smraw[];
    Smem* s = reinterpret_cast<Smem*>(smraw);

    const int tid  = threadIdx.x;
    const int u    = tid & 15;
    const int g    = tid >> 4;        // 24 groups; dir flips at g==12 (even ->
    const int dir  = (g >= NB);       //  warps never straddle directions)
    const int elem = dir ? g - NB : g;
    const int gbase = blockIdx.x * NB;

    // Stage layer-0 input x[B,T,3] into actA channels 0..3 (ch3 zeroed).
    // Tail CTA: invalid elems zero-filled (finite math, stores guarded below).
    for (int i = tid; i < NB * T_ * 4; i += NTHR) {
        int e = i >> 8; int r = i & 255; int t = r >> 2; int c = r & 3;
        float v = 0.f;
        if (c < 3 && gbase + e < B_)
            v = x[((size_t)(gbase + e)) * (T_ * 3) + t * 3 + c];
        s->actA[e][t * 32 + c] = v;
    }
    // Stage classifier weights once (unscaled).
    for (int i = tid; i < 128; i += NTHR) s->wcw[i >> 5][i & 31] = Wc[i];
    if (tid < 4) s->wcb[tid] = bc[tid];

    // Layer 0 (F=3, padded to 4 -> KP=2): actA -> actB
    stage_layer(s, Wi1, Wh1, bi1, bh1, 3, 2, tid);
    __syncthreads();
    run_layer<2>(s, s->actA, s->actB, elem, dir, u);
    __syncthreads();

    // Layers 1..5 (F=32, KP=16), ping-pong. Final output lands in actA.
#pragma unroll 1
    for (int l = 0; l < 5; l++) {
        stage_layer(s, Wi5 + (size_t)l * 3072, Wh5 + (size_t)l * 1536,
                    bi5 + (size_t)l * 96, bh5 + (size_t)l * 96, 32, 16, tid);
        __syncthreads();
        if (l & 1) run_layer<16>(s, s->actA, s->actB, elem, dir, u);
        else       run_layer<16>(s, s->actB, s->actA, elem, dir, u);
        __syncthreads();
    }

    // Classifier + softmax, straight from smem to d_out (coalesced float4).
    for (int i = tid; i < NB * T_; i += NTHR) {
        int e = i >> 6, t = i & 63;
        if (gbase + e >= B_) continue;
        const u64* yp = (const u64*)&s->actA[e][t * 32];
        const u64* w0 = (const u64*)&s->wcw[0][0];
        const u64* w1 = (const u64*)&s->wcw[1][0];
        const u64* w2 = (const u64*)&s->wcw[2][0];
        const u64* w3 = (const u64*)&s->wcw[3][0];
        u64 a0 = 0, a1 = 0, a2 = 0, a3 = 0;
#pragma unroll
        for (int k = 0; k < 16; k++) {
            u64 yv = yp[k];
            a0 = ffma2(w0[k], yv, a0);
            a1 = ffma2(w1[k], yv, a1);
            a2 = ffma2(w2[k], yv, a2);
            a3 = ffma2(w3[k], yv, a3);
        }
        float l0 = hadd(a0) + s->wcb[0];
        float l1 = hadd(a1) + s->wcb[1];
        float l2 = hadd(a2) + s->wcb[2];
        float l3 = hadd(a3) + s->wcb[3];
        float m  = fmaxf(fmaxf(l0, l1), fmaxf(l2, l3));
        float e0 = __expf(l0 - m), e1 = __expf(l1 - m);
        float e2 = __expf(l2 - m), e3 = __expf(l3 - m);
        float rs = __fdividef(1.f, e0 + e1 + e2 + e3);
        float4 o = make_float4(e0 * rs, e1 * rs, e2 * rs, e3 * rs);
        reinterpret_cast<float4*>(out)[((size_t)(gbase + e)) * T_ + t] = o;
    }
}

extern "C" void kernel_launch(void* const* d_in, const int* in_sizes, int n_in,
                              void* d_out, int out_size)
{
    const float* x   = (const float*)d_in[0];
    const float* Wi1 = (const float*)d_in[1];
    const float* Wh1 = (const float*)d_in[2];
    const float* bi1 = (const float*)d_in[3];
    const float* bh1 = (const float*)d_in[4];
    const float* Wi5 = (const float*)d_in[5];
    const float* Wh5 = (const float*)d_in[6];
    const float* bi5 = (const float*)d_in[7];
    const float* bh5 = (const float*)d_in[8];
    const float* Wc  = (const float*)d_in[9];
    const float* bc  = (const float*)d_in[10];
    float* out = (float*)d_out;

    static bool once = []() {
        cudaFuncSetAttribute(fused_gru,
            cudaFuncAttributeMaxDynamicSharedMemorySize, (int)sizeof(Smem));
        return true;
    }();
    (void)once;

    fused_gru<<<(B_ + NB - 1) / NB, NTHR, sizeof(Smem)>>>(
        x, Wi1, Wh1, bi1, bh1, Wi5, Wh5, bi5, bh5, Wc, bc, out);
}

// round 10
// speedup vs baseline: 1.0142x; 1.0142x over previous
#include <cuda_runtime.h>

#define B_    16384
#define T_    64
#define NB    12         // batch elems per CTA
#define NTHR  384        // 24 groups (12 elems x 2 dirs) x 16 lanes
#define EPAD  2052       // floats per elem tile: 64*32, padded, 16B-aligned stride

typedef unsigned long long u64;

#define L2E 1.4426950408889634f

struct __align__(16) Smem {
    u64   wi[2][48][18];          // rows 144B (16B-aligned) — LDS.128-able
    u64   wh[2][48][10];          // rows 80B  (16B-aligned) — LDS.128-able
    float actA[NB][EPAD];
    float actB[NB][EPAD];
    float bR[2][16], bZ[2][16], bNX[2][16], bNH[2][16];
    float wcw[4][32];
    float wcb[4];
};

__device__ __forceinline__ u64 pack2(float lo, float hi) {
    u64 r; asm("mov.b64 %0, {%1, %2};" : "=l"(r) : "f"(lo), "f"(hi)); return r;
}
__device__ __forceinline__ void unpack2(u64 d, float& lo, float& hi) {
    asm("mov.b64 {%0, %1}, %2;" : "=f"(lo), "=f"(hi) : "l"(d));
}
__device__ __forceinline__ u64 ffma2(u64 a, u64 b, u64 c) {
    u64 d; asm("fma.rn.f32x2 %0, %1, %2, %3;" : "=l"(d) : "l"(a), "l"(b), "l"(c)); return d;
}
__device__ __forceinline__ float hadd(u64 v) {
    float lo, hi; unpack2(v, lo, hi); return lo + hi;
}
__device__ __forceinline__ float ex2(float x) {
    float r; asm("ex2.approx.ftz.f32 %0, %1;" : "=f"(r) : "f"(x)); return r;
}
__device__ __forceinline__ float rcp(float x) {
    float r; asm("rcp.approx.ftz.f32 %0, %1;" : "=f"(r) : "f"(x)); return r;
}
// s pre-scaled by log2e: sigmoid(x) = 1/(1+2^-s)
__device__ __forceinline__ float sigm2(float s) {
    return rcp(1.f + ex2(-s));
}
// s pre-scaled by 2*log2e: tanh(x) = sign * (1-2^-|s|)/(1+2^-|s|)
__device__ __forceinline__ float tanh2(float s) {
    float a = fabsf(s);
    float e = ex2(-a);
    float t = (1.f - e) * rcp(1.f + e);
    return copysignf(t, s);
}

// Stage one layer's weights into smem as f32x2 pairs, pre-scaled by log2e
// (r,z rows) / 2*log2e (n rows) so gate nonlinearities use raw ex2.
__device__ __forceinline__ void stage_layer(Smem* s,
        const float* __restrict__ Wi, const float* __restrict__ Wh,
        const float* __restrict__ bi, const float* __restrict__ bh,
        int F, int KP, int tid)
{
    for (int i = tid; i < 2 * 48 * KP; i += NTHR) {
        int d = i / (48 * KP); int r = i - d * 48 * KP;
        int row = r / KP, kp = r - row * KP;
        float sc = (row < 32) ? L2E : 2.f * L2E;
        const float* w = Wi + ((size_t)d * 48 + row) * F;
        float lo = w[2 * kp] * sc;
        float hi = (2 * kp + 1 < F) ? w[2 * kp + 1] * sc : 0.f;
        s->wi[d][row][kp] = pack2(lo, hi);
    }
    for (int i = tid; i < 2 * 48 * 8; i += NTHR) {
        int d = i / (48 * 8); int r = i - d * 48 * 8;
        int row = r >> 3, kp = r & 7;
        float sc = (row < 32) ? L2E : 2.f * L2E;
        const float* w = Wh + ((size_t)d * 48 + row) * 16;
        s->wh[d][row][kp] = pack2(w[2 * kp] * sc, w[2 * kp + 1] * sc);
    }
    for (int i = tid; i < 2 * 16; i += NTHR) {
        int d = i >> 4, uu = i & 15;
        s->bR[d][uu]  = (bi[d * 48 + uu]      + bh[d * 48 + uu])      * L2E;
        s->bZ[d][uu]  = (bi[d * 48 + 16 + uu] + bh[d * 48 + 16 + uu]) * L2E;
        s->bNX[d][uu] = bi[d * 48 + 32 + uu] * 2.f * L2E;
        s->bNH[d][uu] = bh[d * 48 + 32 + uu] * 2.f * L2E;
    }
}

// One bidirectional GRU layer. Lane u of 16-lane group (elem,dir) owns hidden
// unit u. Recurrence via register shfl (width 16). r/z weights in registers;
// n-gate weights streamed from smem as LDS.128 (conflict-free broadcast).
// Input gemm for step t+1 computed inside step t (software pipeline).
template <int KP>
__device__ __forceinline__ void run_layer(Smem* s,
        const float (*rd)[EPAD], float (*wr)[EPAD],
        int elem, int dir, int u)
{
    u64 wir[KP], wiz[KP];
#pragma unroll
    for (int k = 0; k < KP; k++) {
        wir[k] = s->wi[dir][u][k];
        wiz[k] = s->wi[dir][16 + u][k];
    }
    u64 whr[8], whz[8];
#pragma unroll
    for (int k = 0; k < 8; k++) {
        whr[k] = s->wh[dir][u][k];
        whz[k] = s->wh[dir][16 + u][k];
    }
    const ulonglong2* __restrict__ winp = (const ulonglong2*)&s->wi[dir][32 + u][0]; // streamed LDS.128
    const ulonglong2* __restrict__ whnp = (const ulonglong2*)&s->wh[dir][32 + u][0]; // streamed LDS.128
    const float br  = s->bR[dir][u],  bz  = s->bZ[dir][u];
    const float bnx = s->bNX[dir][u], bnh = s->bNH[dir][u];
    const int wcol = dir * 16 + u;
    const int stp  = dir ? -1 : 1;

    u64 xar, xaz, xan;
    // x-gemm for step t (biases folded into accumulator init); LDS.128 x reads
    auto xgemm = [&](int t) {
        const ulonglong2* xp = (const ulonglong2*)&rd[elem][t * 32];
        u64 r = pack2(br, 0.f), z = pack2(bz, 0.f), n = pack2(bnx, 0.f);
#pragma unroll
        for (int k = 0; k < KP / 2; k++) {
            ulonglong2 xv = xp[k];
            ulonglong2 wn = winp[k];
            r = ffma2(wir[2*k],   xv.x, r);
            z = ffma2(wiz[2*k],   xv.x, z);
            n = ffma2(wn.x,       xv.x, n);
            r = ffma2(wir[2*k+1], xv.y, r);
            z = ffma2(wiz[2*k+1], xv.y, z);
            n = ffma2(wn.y,       xv.y, n);
        }
        xar = r; xaz = z; xan = n;
    };

    int t = dir ? (T_ - 1) : 0;
    xgemm(t);

    // ---- peeled first step (h == 0, no recurrence) ----
    float h;
    {
        float r = sigm2(hadd(xar));
        float z = sigm2(hadd(xaz));
        float n = tanh2(fmaf(r, bnh, hadd(xan)));
        h = fmaf(-z, n, n);                      // (1-z)*n
        wr[elem][t * 32 + wcol] = h;
        t += stp;
        xgemm(t);                                // pipeline: x-acc for step 1
    }

#pragma unroll 1
    for (int ti = 1; ti < T_; ++ti) {
        // recurrent gemm: gather group's h via shfl (width 16), pack to f32x2.
        // r/z accumulators seeded from x-accs (saves the merge add2s);
        // n-gate h-acc seeded with bnh (saves the tail FADD).
        u64 arh = xar, azh = xaz, anh = pack2(bnh, 0.f);
#pragma unroll
        for (int k = 0; k < 4; k++) {
            ulonglong2 wn = whnp[k];
            float h0 = __shfl_sync(0xffffffffu, h, 4 * k,     16);
            float h1 = __shfl_sync(0xffffffffu, h, 4 * k + 1, 16);
            float h2 = __shfl_sync(0xffffffffu, h, 4 * k + 2, 16);
            float h3 = __shfl_sync(0xffffffffu, h, 4 * k + 3, 16);
            u64 hv0 = pack2(h0, h1);
            u64 hv1 = pack2(h2, h3);
            arh = ffma2(whr[2*k],   hv0, arh);
            azh = ffma2(whz[2*k],   hv0, azh);
            anh = ffma2(wn.x,       hv0, anh);
            arh = ffma2(whr[2*k+1], hv1, arh);
            azh = ffma2(whz[2*k+1], hv1, azh);
            anh = ffma2(wn.y,       hv1, anh);
        }
        float arf  = hadd(arh);
        float azf  = hadd(azh);
        float anxf = hadd(xan);
        float anhf = hadd(anh);

        // pipeline: x-acc for next step (independent -> fills gate stalls)
        int tn = (ti == T_ - 1) ? t : t + stp;
        xgemm(tn);

        float r = sigm2(arf);
        float z = sigm2(azf);
        float n = tanh2(fmaf(r, anhf, anxf));
        h = fmaf(z, h - n, n);                   // (1-z)*n + z*h
        wr[elem][t * 32 + wcol] = h;
        t = tn;
    }
}

extern "C" __global__ void __launch_bounds__(NTHR)
fused_gru(const float* __restrict__ x,
          const float* __restrict__ Wi1, const float* __restrict__ Wh1,
          const float* __restrict__ bi1, const float* __restrict__ bh1,
          const float* __restrict__ Wi5, const float* __restrict__ Wh5,
          const float* __restrict__ bi5, const float* __restrict__ bh5,
          const float* __restrict__ Wc,  const float* __restrict__ bc,
          float* __restrict__ out)
{
    extern __shared__ __align__(16) unsigned char smraw[];
    Smem* s = reinterpret_cast<Smem*>(smraw);

    const int tid  = threadIdx.x;
    const int u    = tid & 15;
    const int g    = tid >> 4;        // 24 groups; dir flips at g==12 (even ->
    const int dir  = (g >= NB);       //  warps never straddle directions)
    const int elem = dir ? g - NB : g;
    const int gbase = blockIdx.x * NB;

    // Stage layer-0 input x[B,T,3] into actA channels 0..3 (ch3 zeroed).
    // Tail CTA: invalid elems zero-filled (finite math, stores guarded below).
    for (int i = tid; i < NB * T_ * 4; i += NTHR) {
        int e = i >> 8; int r = i & 255; int t = r >> 2; int c = r & 3;
        float v = 0.f;
        if (c < 3 && gbase + e < B_)
            v = x[((size_t)(gbase + e)) * (T_ * 3) + t * 3 + c];
        s->actA[e][t * 32 + c] = v;
    }
    // Stage classifier weights once (unscaled).
    for (int i = tid; i < 128; i += NTHR) s->wcw[i >> 5][i & 31] = Wc[i];
    if (tid < 4) s->wcb[tid] = bc[tid];

    // Layer 0 (F=3, padded to 4 -> KP=2): actA -> actB
    stage_layer(s, Wi1, Wh1, bi1, bh1, 3, 2, tid);
    __syncthreads();
    run_layer<2>(s, s->actA, s->actB, elem, dir, u);
    __syncthreads();

    // Layers 1..5 (F=32, KP=16), ping-pong. Final output lands in actA.
#pragma unroll 1
    for (int l = 0; l < 5; l++) {
        stage_layer(s, Wi5 + (size_t)l * 3072, Wh5 + (size_t)l * 1536,
                    bi5 + (size_t)l * 96, bh5 + (size_t)l * 96, 32, 16, tid);
        __syncthreads();
        if (l & 1) run_layer<16>(s, s->actA, s->actB, elem, dir, u);
        else       run_layer<16>(s, s->actB, s->actA, elem, dir, u);
        __syncthreads();
    }

    // Classifier + softmax, straight from smem to d_out (coalesced float4).
    for (int i = tid; i < NB * T_; i += NTHR) {
        int e = i >> 6, t = i & 63;
        if (gbase + e >= B_) continue;
        const ulonglong2* yp = (const ulonglong2*)&s->actA[e][t * 32];
        const ulonglong2* w0 = (const ulonglong2*)&s->wcw[0][0];
        const ulonglong2* w1 = (const ulonglong2*)&s->wcw[1][0];
        const ulonglong2* w2 = (const ulonglong2*)&s->wcw[2][0];
        const ulonglong2* w3 = (const ulonglong2*)&s->wcw[3][0];
        u64 a0 = 0, a1 = 0, a2 = 0, a3 = 0;
#pragma unroll
        for (int k = 0; k < 8; k++) {
            ulonglong2 yv = yp[k];
            ulonglong2 c0 = w0[k], c1 = w1[k], c2 = w2[k], c3 = w3[k];
            a0 = ffma2(c0.x, yv.x, a0); a0 = ffma2(c0.y, yv.y, a0);
            a1 = ffma2(c1.x, yv.x, a1); a1 = ffma2(c1.y, yv.y, a1);
            a2 = ffma2(c2.x, yv.x, a2); a2 = ffma2(c2.y, yv.y, a2);
            a3 = ffma2(c3.x, yv.x, a3); a3 = ffma2(c3.y, yv.y, a3);
        }
        float l0 = hadd(a0) + s->wcb[0];
        float l1 = hadd(a1) + s->wcb[1];
        float l2 = hadd(a2) + s->wcb[2];
        float l3 = hadd(a3) + s->wcb[3];
        float m  = fmaxf(fmaxf(l0, l1), fmaxf(l2, l3));
        float e0 = __expf(l0 - m), e1 = __expf(l1 - m);
        float e2 = __expf(l2 - m), e3 = __expf(l3 - m);
        float rs = __fdividef(1.f, e0 + e1 + e2 + e3);
        float4 o = make_float4(e0 * rs, e1 * rs, e2 * rs, e3 * rs);
        reinterpret_cast<float4*>(out)[((size_t)(gbase + e)) * T_ + t] = o;
    }
}

extern "C" void kernel_launch(void* const* d_in, const int* in_sizes, int n_in,
                              void* d_out, int out_size)
{
    const float* x   = (const float*)d_in[0];
    const float* Wi1 = (const float*)d_in[1];
    const float* Wh1 = (const float*)d_in[2];
    const float* bi1 = (const float*)d_in[3];
    const float* bh1 = (const float*)d_in[4];
    const float* Wi5 = (const float*)d_in[5];
    const float* Wh5 = (const float*)d_in[6];
    const float* bi5 = (const float*)d_in[7];
    const float* bh5 = (const float*)d_in[8];
    const float* Wc  = (const float*)d_in[9];
    const float* bc  = (const float*)d_in[10];
    float* out = (float*)d_out;

    static bool once = []() {
        cudaFuncSetAttribute(fused_gru,
            cudaFuncAttributeMaxDynamicSharedMemorySize, (int)sizeof(Smem));
        return true;
    }();
    (void)once;

    fused_gru<<<(B_ + NB - 1) / NB, NTHR, sizeof(Smem)>>>(
        x, Wi1, Wh1, bi1, bh1, Wi5, Wh5, bi5, bh5, Wc, bc, out);
}

// round 11
// speedup vs baseline: 1.1598x; 1.1436x over previous
#include <cuda_runtime.h>

#define B_    16384
#define T_    64
#define NB    12         // batch elems per CTA
#define CH    3          // chains per 16-lane group (3 elems, same dir)
#define NTHR  128        // 8 groups x 16 lanes; 4 warps = 1 per SMSP
#define EPAD  2052       // floats per elem tile: 64*32 + pad, 16B-aligned

typedef unsigned long long u64;

#define L2E 1.4426950408889634f

struct __align__(16) Smem {
    u64   wi[2][48][16];          // [dir][gate_row][k-pair]
    u64   wh[2][48][8];
    float actA[NB][EPAD];
    float actB[NB][EPAD];
    float bR[2][16], bZ[2][16], bNX[2][16], bNH[2][16];
    float wcw[4][32];
    float wcb[4];
};

__device__ __forceinline__ u64 pack2(float lo, float hi) {
    u64 r; asm("mov.b64 %0, {%1, %2};" : "=l"(r) : "f"(lo), "f"(hi)); return r;
}
__device__ __forceinline__ void unpack2(u64 d, float& lo, float& hi) {
    asm("mov.b64 {%0, %1}, %2;" : "=f"(lo), "=f"(hi) : "l"(d));
}
__device__ __forceinline__ u64 ffma2(u64 a, u64 b, u64 c) {
    u64 d; asm("fma.rn.f32x2 %0, %1, %2, %3;" : "=l"(d) : "l"(a), "l"(b), "l"(c)); return d;
}
__device__ __forceinline__ float hadd(u64 v) {
    float lo, hi; unpack2(v, lo, hi); return lo + hi;
}
__device__ __forceinline__ float ex2(float x) {
    float r; asm("ex2.approx.ftz.f32 %0, %1;" : "=f"(r) : "f"(x)); return r;
}
__device__ __forceinline__ float rcp(float x) {
    float r; asm("rcp.approx.ftz.f32 %0, %1;" : "=f"(r) : "f"(x)); return r;
}
// s pre-scaled by log2e: sigmoid(x) = 1/(1+2^-s)
__device__ __forceinline__ float sigm2(float s) {
    return rcp(1.f + ex2(-s));
}
// s pre-scaled by 2*log2e: tanh(x) = sign * (1-2^-|s|)/(1+2^-|s|)
__device__ __forceinline__ float tanh2(float s) {
    float a = fabsf(s);
    float e = ex2(-a);
    float t = (1.f - e) * rcp(1.f + e);
    return copysignf(t, s);
}

// Stage one layer's weights into smem as f32x2 pairs, pre-scaled by log2e
// (r,z rows) / 2*log2e (n rows) so gate nonlinearities use raw ex2.
__device__ __forceinline__ void stage_layer(Smem* s,
        const float* __restrict__ Wi, const float* __restrict__ Wh,
        const float* __restrict__ bi, const float* __restrict__ bh,
        int F, int KP, int tid)
{
    for (int i = tid; i < 2 * 48 * KP; i += NTHR) {
        int d = i / (48 * KP); int r = i - d * 48 * KP;
        int row = r / KP, kp = r - row * KP;
        float sc = (row < 32) ? L2E : 2.f * L2E;
        const float* w = Wi + ((size_t)d * 48 + row) * F;
        float lo = w[2 * kp] * sc;
        float hi = (2 * kp + 1 < F) ? w[2 * kp + 1] * sc : 0.f;
        s->wi[d][row][kp] = pack2(lo, hi);
    }
    for (int i = tid; i < 2 * 48 * 8; i += NTHR) {
        int d = i / (48 * 8); int r = i - d * 48 * 8;
        int row = r >> 3, kp = r & 7;
        float sc = (row < 32) ? L2E : 2.f * L2E;
        const float* w = Wh + ((size_t)d * 48 + row) * 16;
        s->wh[d][row][kp] = pack2(w[2 * kp] * sc, w[2 * kp + 1] * sc);
    }
    for (int i = tid; i < 2 * 16; i += NTHR) {
        int d = i >> 4, uu = i & 15;
        s->bR[d][uu]  = (bi[d * 48 + uu]      + bh[d * 48 + uu])      * L2E;
        s->bZ[d][uu]  = (bi[d * 48 + 16 + uu] + bh[d * 48 + 16 + uu]) * L2E;
        s->bNX[d][uu] = bi[d * 48 + 32 + uu] * 2.f * L2E;
        s->bNH[d][uu] = bh[d * 48 + 32 + uu] * 2.f * L2E;
    }
}

// One bidirectional GRU layer. Lane u of a 16-lane group owns hidden unit u
// of CH independent chains (3 batch elems, same dir) — weights shared, ILP
// tripled so one warp/SMSP keeps the FMA pipe fed through the gate tails.
// All weights in registers. Recurrence h gathered via width-16 shfl.
template <int KP>
__device__ __forceinline__ void run_layer(Smem* s,
        const float (*rd)[EPAD], float (*wr)[EPAD],
        int ebase, int dir, int u)
{
    u64 wir[KP], wiz[KP], win[KP];
#pragma unroll
    for (int k = 0; k < KP; k++) {
        wir[k] = s->wi[dir][u][k];
        wiz[k] = s->wi[dir][16 + u][k];
        win[k] = s->wi[dir][32 + u][k];
    }
    u64 whr[8], whz[8], whn[8];
#pragma unroll
    for (int k = 0; k < 8; k++) {
        whr[k] = s->wh[dir][u][k];
        whz[k] = s->wh[dir][16 + u][k];
        whn[k] = s->wh[dir][32 + u][k];
    }
    const float br  = s->bR[dir][u],  bz  = s->bZ[dir][u];
    const float bnx = s->bNX[dir][u], bnh = s->bNH[dir][u];
    const int wcol = dir * 16 + u;
    const int stp  = dir ? -1 : 1;

    u64 xar[CH], xaz[CH], xan[CH];
    float h[CH];

    // x-gemm for chain c at time t (biases folded into accumulator init)
    auto xgemm = [&](int c, int t) {
        const ulonglong2* xp = (const ulonglong2*)&rd[ebase + c][t * 32];
        u64 r = pack2(br, 0.f), z = pack2(bz, 0.f), n = pack2(bnx, 0.f);
#pragma unroll
        for (int k = 0; k < KP / 2; k++) {
            ulonglong2 xv = xp[k];
            r = ffma2(wir[2*k],   xv.x, r);
            z = ffma2(wiz[2*k],   xv.x, z);
            n = ffma2(win[2*k],   xv.x, n);
            r = ffma2(wir[2*k+1], xv.y, r);
            z = ffma2(wiz[2*k+1], xv.y, z);
            n = ffma2(win[2*k+1], xv.y, n);
        }
        xar[c] = r; xaz[c] = z; xan[c] = n;
    };

    int t = dir ? (T_ - 1) : 0;
#pragma unroll
    for (int c = 0; c < CH; c++) xgemm(c, t);

    // ---- peeled first step (h == 0, no recurrence) ----
#pragma unroll
    for (int c = 0; c < CH; c++) {
        float r = sigm2(hadd(xar[c]));
        float z = sigm2(hadd(xaz[c]));
        float n = tanh2(fmaf(r, bnh, hadd(xan[c])));
        h[c] = fmaf(-z, n, n);                   // (1-z)*n
        wr[ebase + c][t * 32 + wcol] = h[c];
    }
    t += stp;
#pragma unroll
    for (int c = 0; c < CH; c++) xgemm(c, t);

#pragma unroll 1
    for (int ti = 1; ti < T_; ++ti) {
        // recurrent gemm for all chains (independent -> interleaved by ptxas)
        float arf[CH], azf[CH], anxf[CH], anhf[CH];
#pragma unroll
        for (int c = 0; c < CH; c++) {
            u64 arh = xar[c], azh = xaz[c], anh = pack2(bnh, 0.f);
#pragma unroll
            for (int k = 0; k < 4; k++) {
                float h0 = __shfl_sync(0xffffffffu, h[c], 4 * k,     16);
                float h1 = __shfl_sync(0xffffffffu, h[c], 4 * k + 1, 16);
                float h2 = __shfl_sync(0xffffffffu, h[c], 4 * k + 2, 16);
                float h3 = __shfl_sync(0xffffffffu, h[c], 4 * k + 3, 16);
                u64 hv0 = pack2(h0, h1);
                u64 hv1 = pack2(h2, h3);
                arh = ffma2(whr[2*k],   hv0, arh);
                azh = ffma2(whz[2*k],   hv0, azh);
                anh = ffma2(whn[2*k],   hv0, anh);
                arh = ffma2(whr[2*k+1], hv1, arh);
                azh = ffma2(whz[2*k+1], hv1, azh);
                anh = ffma2(whn[2*k+1], hv1, anh);
            }
            arf[c]  = hadd(arh);
            azf[c]  = hadd(azh);
            anxf[c] = hadd(xan[c]);
            anhf[c] = hadd(anh);
        }

        // pipeline: x-accs for next step (fills this step's gate stalls)
        int tn = (ti == T_ - 1) ? t : t + stp;
#pragma unroll
        for (int c = 0; c < CH; c++) xgemm(c, tn);

#pragma unroll
        for (int c = 0; c < CH; c++) {
            float r = sigm2(arf[c]);
            float z = sigm2(azf[c]);
            float n = tanh2(fmaf(r, anhf[c], anxf[c]));
            h[c] = fmaf(z, h[c] - n, n);         // (1-z)*n + z*h
            wr[ebase + c][t * 32 + wcol] = h[c];
        }
        t = tn;
    }
}

extern "C" __global__ void __launch_bounds__(NTHR, 1)
fused_gru(const float* __restrict__ x,
          const float* __restrict__ Wi1, const float* __restrict__ Wh1,
          const float* __restrict__ bi1, const float* __restrict__ bh1,
          const float* __restrict__ Wi5, const float* __restrict__ Wh5,
          const float* __restrict__ bi5, const float* __restrict__ bh5,
          const float* __restrict__ Wc,  const float* __restrict__ bc,
          float* __restrict__ out)
{
    extern __shared__ __align__(16) unsigned char smraw[];
    Smem* s = reinterpret_cast<Smem*>(smraw);

    const int tid   = threadIdx.x;
    const int u     = tid & 15;
    const int g     = tid >> 4;          // 8 groups; group-uniform dir
    const int dir   = g & 1;
    const int ebase = (g >> 1) * CH;     // elems ebase..ebase+2
    const int gbase = blockIdx.x * NB;

    // Stage layer-0 input x[B,T,3] into actA channels 0..3 (ch3 zeroed).
    // Tail CTA: invalid elems zero-filled (finite math; stores guarded below).
    for (int i = tid; i < NB * T_ * 4; i += NTHR) {
        int e = i >> 8; int r = i & 255; int t = r >> 2; int c = r & 3;
        float v = 0.f;
        if (c < 3 && gbase + e < B_)
            v = x[((size_t)(gbase + e)) * (T_ * 3) + t * 3 + c];
        s->actA[e][t * 32 + c] = v;
    }
    // Stage classifier weights once (unscaled).
    for (int i = tid; i < 128; i += NTHR) s->wcw[i >> 5][i & 31] = Wc[i];
    if (tid < 4) s->wcb[tid] = bc[tid];

    // Layer 0 (F=3, padded to 4 -> KP=2): actA -> actB
    stage_layer(s, Wi1, Wh1, bi1, bh1, 3, 2, tid);
    __syncthreads();
    run_layer<2>(s, s->actA, s->actB, ebase, dir, u);
    __syncthreads();

    // Layers 1..5 (F=32, KP=16), ping-pong. Final output lands in actA.
#pragma unroll 1
    for (int l = 0; l < 5; l++) {
        stage_layer(s, Wi5 + (size_t)l * 3072, Wh5 + (size_t)l * 1536,
                    bi5 + (size_t)l * 96, bh5 + (size_t)l * 96, 32, 16, tid);
        __syncthreads();
        if (l & 1) run_layer<16>(s, s->actA, s->actB, ebase, dir, u);
        else       run_layer<16>(s, s->actB, s->actA, ebase, dir, u);
        __syncthreads();
    }

    // Classifier + softmax, straight from smem to d_out (coalesced float4).
    for (int i = tid; i < NB * T_; i += NTHR) {
        int e = i >> 6, t = i & 63;
        if (gbase + e >= B_) continue;
        const ulonglong2* yp = (const ulonglong2*)&s->actA[e][t * 32];
        const ulonglong2* w0 = (const ulonglong2*)&s->wcw[0][0];
        const ulonglong2* w1 = (const ulonglong2*)&s->wcw[1][0];
        const ulonglong2* w2 = (const ulonglong2*)&s->wcw[2][0];
        const ulonglong2* w3 = (const ulonglong2*)&s->wcw[3][0];
        u64 a0 = 0, a1 = 0, a2 = 0, a3 = 0;
#pragma unroll
        for (int k = 0; k < 8; k++) {
            ulonglong2 yv = yp[k];
            ulonglong2 c0 = w0[k], c1 = w1[k], c2 = w2[k], c3 = w3[k];
            a0 = ffma2(c0.x, yv.x, a0); a0 = ffma2(c0.y, yv.y, a0);
            a1 = ffma2(c1.x, yv.x, a1); a1 = ffma2(c1.y, yv.y, a1);
            a2 = ffma2(c2.x, yv.x, a2); a2 = ffma2(c2.y, yv.y, a2);
            a3 = ffma2(c3.x, yv.x, a3); a3 = ffma2(c3.y, yv.y, a3);
        }
        float l0 = hadd(a0) + s->wcb[0];
        float l1 = hadd(a1) + s->wcb[1];
        float l2 = hadd(a2) + s->wcb[2];
        float l3 = hadd(a3) + s->wcb[3];
        float m  = fmaxf(fmaxf(l0, l1), fmaxf(l2, l3));
        float e0 = __expf(l0 - m), e1 = __expf(l1 - m);
        float e2 = __expf(l2 - m), e3 = __expf(l3 - m);
        float rs = __fdividef(1.f, e0 + e1 + e2 + e3);
        float4 o = make_float4(e0 * rs, e1 * rs, e2 * rs, e3 * rs);
        reinterpret_cast<float4*>(out)[((size_t)(gbase + e)) * T_ + t] = o;
    }
}

extern "C" void kernel_launch(void* const* d_in, const int* in_sizes, int n_in,
                              void* d_out, int out_size)
{
    const float* x   = (const float*)d_in[0];
    const float* Wi1 = (const float*)d_in[1];
    const float* Wh1 = (const float*)d_in[2];
    const float* bi1 = (const float*)d_in[3];
    const float* bh1 = (const float*)d_in[4];
    const float* Wi5 = (const float*)d_in[5];
    const float* Wh5 = (const float*)d_in[6];
    const float* bi5 = (const float*)d_in[7];
    const float* bh5 = (const float*)d_in[8];
    const float* Wc  = (const float*)d_in[9];
    const float* bc  = (const float*)d_in[10];
    float* out = (float*)d_out;

    static bool once = []() {
        cudaFuncSetAttribute(fused_gru,
            cudaFuncAttributeMaxDynamicSharedMemorySize, (int)sizeof(Smem));
        return true;
    }();
    (void)once;

    fused_gru<<<(B_ + NB - 1) / NB, NTHR, sizeof(Smem)>>>(
        x, Wi1, Wh1, bi1, bh1, Wi5, Wh5, bi5, bh5, Wc, bc, out);
}